// round 1
// baseline (speedup 1.0000x reference)
#include <cuda_runtime.h>
#include <cuda_bf16.h>

// Problem constants (fixed shapes per reference)
#define N_NODES  100000
#define E_EDGES  1000000
#define IN_F     64
#define OUT_F    64
#define N_REL    16
#define N_BASES  8

#define CHUNK    2048
#define LIST_CAP 512

// Basis-combined relation weights. Layout follows the reference's
// reinterpreting reshape: d_W is Mflat with M[i,r,o] at [i*1024 + r*64 + o],
// and the effective W[r,k,o] = d_W[r*4096 + k*64 + o].
__device__ float d_W[N_REL * IN_F * OUT_F];

// ---------------------------------------------------------------------------
// K1: basis combination.  d_W[idx] with idx = i*1024 + r*64 + o
//     = sum_b w_comp[r,b] * weight_flat[i*512 + b*64 + o]
// ---------------------------------------------------------------------------
__global__ void compute_W_kernel(const float* __restrict__ weight,
                                 const float* __restrict__ w_comp) {
    int idx = blockIdx.x * blockDim.x + threadIdx.x;
    if (idx >= N_REL * IN_F * OUT_F) return;
    int i = idx >> 10;          // /1024
    int r = (idx >> 6) & 15;
    int o = idx & 63;
    float s = 0.f;
#pragma unroll
    for (int b = 0; b < N_BASES; b++)
        s += w_comp[r * N_BASES + b] * weight[i * 512 + b * 64 + o];
    d_W[idx] = s;
}

// ---------------------------------------------------------------------------
// K2: h_new = relu(h) into out[0 : N*64), zero out[N*64 : 2*N*64)  (h2 accum)
// ---------------------------------------------------------------------------
__global__ void relu_zero_kernel(const float4* __restrict__ h, float4* out) {
    int i = blockIdx.x * blockDim.x + threadIdx.x;
    const int n4 = N_NODES * IN_F / 4;
    if (i >= n4) return;
    float4 v = h[i];
    v.x = fmaxf(v.x, 0.f);
    v.y = fmaxf(v.y, 0.f);
    v.z = fmaxf(v.z, 0.f);
    v.w = fmaxf(v.w, 0.f);
    out[i] = v;
    out[n4 + i] = make_float4(0.f, 0.f, 0.f, 0.f);
}

// ---------------------------------------------------------------------------
// K3: per-relation specialized scatter.
//   grid = (ceil(E/CHUNK), N_REL).  CTA (c, r): load W[r] into SMEM,
//   compact edges in chunk c with rel==r, then warps process 4 edges at a
//   time: msg = h[src] @ W[r] with h broadcast via shfl, accumulation in
//   packed f32x2, scatter via red.global.add.v2.f32.
// ---------------------------------------------------------------------------
__global__ void __launch_bounds__(256, 4)
scatter_msg_kernel(const float* __restrict__ h,
                   const int* __restrict__ src,
                   const int* __restrict__ dst,
                   const int* __restrict__ rel,
                   float* __restrict__ h2) {
    __shared__ float Ws[IN_F * OUT_F];   // 16 KB: W[r]
    __shared__ int   list[LIST_CAP];
    __shared__ int   cnt;

    const int r   = blockIdx.y;
    const int tid = threadIdx.x;
    if (tid == 0) cnt = 0;

    // Load W[r] (4096 floats) into SMEM, vectorized.
    {
        const float4* Wg  = (const float4*)(d_W + r * 4096);
        float4*       Ws4 = (float4*)Ws;
#pragma unroll
        for (int j = tid; j < 1024; j += 256) Ws4[j] = Wg[j];
    }
    __syncthreads();

    // Scan this chunk for edges with rel == r, compact into SMEM list.
    const int base = blockIdx.x * CHUNK;
#pragma unroll 2
    for (int j = tid; j < CHUNK; j += 256) {
        int e = base + j;
        if (e < E_EDGES && rel[e] == r) {
            int p = atomicAdd(&cnt, 1);
            if (p < LIST_CAP) list[p] = e;
        }
    }
    __syncthreads();

    const int n    = min(cnt, LIST_CAP);
    const int wid  = tid >> 5;
    const int lane = tid & 31;
    const unsigned long long* Ws2 = (const unsigned long long*)Ws;

    for (int gb = wid * 4; gb < n; gb += 8 * 4) {
        const int m = min(4, n - gb);
        float2 hv[4];
        int    dn[4];
#pragma unroll
        for (int e = 0; e < 4; e++) {
            if (e < m) {
                int eid = list[gb + e];
                int s   = __ldg(&src[eid]);
                dn[e]   = __ldg(&dst[eid]);
                hv[e]   = *(const float2*)(h + s * 64 + 2 * lane);
            } else {
                hv[e] = make_float2(0.f, 0.f);
                dn[e] = 0;
            }
        }

        unsigned long long acc[4] = {0ull, 0ull, 0ull, 0ull};
#pragma unroll
        for (int kk = 0; kk < 32; kk++) {
            // w0 = W[2kk][2l..2l+1], w1 = W[2kk+1][2l..2l+1], already packed
            unsigned long long w0 = Ws2[(2 * kk) * 32 + lane];
            unsigned long long w1 = Ws2[(2 * kk + 1) * 32 + lane];
#pragma unroll
            for (int e = 0; e < 4; e++) {
                float hx = __shfl_sync(0xffffffffu, hv[e].x, kk);
                float hy = __shfl_sync(0xffffffffu, hv[e].y, kk);
                unsigned long long hxx, hyy;
                asm("mov.b64 %0, {%1, %1};" : "=l"(hxx) : "f"(hx));
                asm("mov.b64 %0, {%1, %1};" : "=l"(hyy) : "f"(hy));
                asm("fma.rn.f32x2 %0, %1, %2, %0;" : "+l"(acc[e]) : "l"(hxx), "l"(w0));
                asm("fma.rn.f32x2 %0, %1, %2, %0;" : "+l"(acc[e]) : "l"(hyy), "l"(w1));
            }
        }

#pragma unroll
        for (int e = 0; e < 4; e++) {
            if (e < m) {
                float ax, ay;
                asm("mov.b64 {%0, %1}, %2;" : "=f"(ax), "=f"(ay) : "l"(acc[e]));
                float* p = h2 + dn[e] * 64 + 2 * lane;
                asm volatile("red.global.add.v2.f32 [%0], {%1, %2};"
                             :: "l"(p), "f"(ax), "f"(ay) : "memory");
            }
        }
    }
}

// ---------------------------------------------------------------------------
extern "C" void kernel_launch(void* const* d_in, const int* in_sizes, int n_in,
                              void* d_out, int out_size) {
    const float* h      = (const float*)d_in[0];
    const float* weight = (const float*)d_in[1];
    const float* w_comp = (const float*)d_in[2];
    const int*   src    = (const int*)d_in[3];
    const int*   dst    = (const int*)d_in[4];
    const int*   rel    = (const int*)d_in[5];
    float* out = (float*)d_out;          // [h_new (N*64) | h2 (N*64)]
    float* h2  = out + N_NODES * IN_F;

    // K1: basis combination (65536 outputs)
    compute_W_kernel<<<(N_REL * IN_F * OUT_F + 255) / 256, 256>>>(weight, w_comp);

    // K2: relu(h) -> out, zero h2
    relu_zero_kernel<<<(N_NODES * IN_F / 4 + 255) / 256, 256>>>(
        (const float4*)h, (float4*)out);

    // K3: edge messages + scatter
    dim3 grid((E_EDGES + CHUNK - 1) / CHUNK, N_REL);
    scatter_msg_kernel<<<grid, 256>>>(h, src, dst, rel, h2);
}